// round 14
// baseline (speedup 1.0000x reference)
#include <cuda_runtime.h>
#include <cstdint>
#include <cstddef>

// ---------------------------------------------------------------------------
// Bidirectional LSTM (Round 14 = Round 10 base + k-quarter recur matmul):
//   1) prepass_kernel: gx = b_lstm + W_ih.(W_enc.x + b_enc) for all t
//      (parallel GEMM), 2 x 1GB staging, dir=1 stored t-reversed. (R10 verbatim)
//   2) recur_kernel: 256 CTAs, 2 seqs/CTA, 2 CTAs/SM. Thread = 4 gate rows x
//      16-h k-quarter x 2 seqs: 4 LDS.128 -> 32 FFMA2 per seq (1:8 ratio,
//      halves the 256-cyc/SMSP LDS issue term). float4 gps stores; gx
//      streamed with running-pointer distance-1 float4 prefetch.
//   3) final_kernel.
// ---------------------------------------------------------------------------

#define T_STEPS 4096
#define HID     64
#define KIN     60
#define ENC     32

__device__ float g_gx0[256ULL * T_STEPS * 256];   // 1 GB, dir 0
__device__ float g_gx1[256ULL * T_STEPS * 256];   // 1 GB, dir 1 (reversed t)
__device__ float g_cfin[2][256][HID];

typedef unsigned long long ull;

__device__ __forceinline__ ull pack2(float lo, float hi) {
    ull u;
    asm("mov.b64 %0, {%1, %2};" : "=l"(u) : "f"(lo), "f"(hi));
    return u;
}
__device__ __forceinline__ void unpack2(ull u, float& lo, float& hi) {
    asm("mov.b64 {%0, %1}, %2;" : "=f"(lo), "=f"(hi) : "l"(u));
}
__device__ __forceinline__ void ffma2(ull& d, ull a, ull b) {
    asm("fma.rn.f32x2 %0, %1, %2, %0;" : "+l"(d) : "l"(a), "l"(b));
}
__device__ __forceinline__ float fast_sigmoid(float x) {
    return __fdividef(1.0f, 1.0f + __expf(-x));
}
__device__ __forceinline__ float fast_tanh(float x) {
    return 1.0f - __fdividef(2.0f, __expf(2.0f * x) + 1.0f);
}

__global__ void pad_kernel() {}

// ---------------------------------------------------------------------------
// Prepass (R10 verbatim): grid 2048 = (b:256) x (chunk:8 of 512 t).
// ---------------------------------------------------------------------------
__global__ void __launch_bounds__(256, 2)
prepass_kernel(const float* __restrict__ cin,
               const float* __restrict__ W_enc, const float* __restrict__ b_enc,
               const float* __restrict__ W_ih_f, const float* __restrict__ b_f,
               const float* __restrict__ W_ih_b, const float* __restrict__ b_b) {
    const int b     = blockIdx.x >> 3;
    const int chunk = blockIdx.x & 7;
    const int t0    = chunk * 512;
    const int tid   = threadIdx.x;
    const int dg    = tid >> 7;
    const int lt    = tid & 127;
    const int r0    = 2 * lt;

    __shared__ __align__(16) float  c_sm[64][KIN];
    __shared__ __align__(16) float  enc_sm[64][ENC];
    __shared__ __align__(8)  float2 wT[30][ENC];

    const float* W_ih = dg ? W_ih_b : W_ih_f;
    const float* bv   = dg ? b_b    : b_f;
    float* gxbase     = dg ? g_gx1  : g_gx0;

    ull wi0[16], wi1[16];
#pragma unroll
    for (int i = 0; i < 16; i++) {
        float2 p = *reinterpret_cast<const float2*>(W_ih + (size_t)r0 * ENC + 2 * i);
        float2 q = *reinterpret_cast<const float2*>(W_ih + (size_t)(r0 + 1) * ENC + 2 * i);
        wi0[i] = pack2(p.x, p.y);
        wi1[i] = pack2(q.x, q.y);
    }
    const float bias0 = bv[r0];
    const float bias1 = bv[r0 + 1];

    for (int idx = tid; idx < 30 * ENC; idx += 256) {
        const int i = idx >> 5, e = idx & 31;
        wT[i][e] = make_float2(W_enc[e * KIN + 2 * i], W_enc[e * KIN + 2 * i + 1]);
    }
    const float benc  = b_enc[tid & 31];
    const int   ewarp = tid >> 5;
    const int   ej    = tid & 31;

    for (int ss = 0; ss < 8; ss++) {
        const int tb = t0 + ss * 64;
        __syncthreads();
        {
            const float* src = cin + ((size_t)b * T_STEPS + tb) * KIN;
            for (int i = tid; i < 64 * KIN; i += 256)
                (&c_sm[0][0])[i] = src[i];
        }
        __syncthreads();

#pragma unroll
        for (int tt = 0; tt < 8; tt++) {
            const int t = ewarp * 8 + tt;
            ull acc = 0ull;
            const float* crow = &c_sm[t][0];
#pragma unroll
            for (int i = 0; i < 15; i++) {
                const ulonglong2 v = *reinterpret_cast<const ulonglong2*>(crow + 4 * i);
                ffma2(acc, *reinterpret_cast<const ull*>(&wT[2 * i][ej]), v.x);
                ffma2(acc, *reinterpret_cast<const ull*>(&wT[2 * i + 1][ej]), v.y);
            }
            float l, h;
            unpack2(acc, l, h);
            enc_sm[t][ej] = benc + l + h;
        }
        __syncthreads();

        for (int tt = 0; tt < 64; tt++) {
            ull a0 = pack2(bias0, 0.0f);
            ull a1 = pack2(bias1, 0.0f);
            const float* erow = &enc_sm[tt][0];
#pragma unroll
            for (int c = 0; c < 8; c++) {
                const ulonglong2 v = *reinterpret_cast<const ulonglong2*>(erow + 4 * c);
                ffma2(a0, wi0[2 * c], v.x); ffma2(a0, wi0[2 * c + 1], v.y);
                ffma2(a1, wi1[2 * c], v.x); ffma2(a1, wi1[2 * c + 1], v.y);
            }
            const int t = tb + tt;
            const int n = dg ? (T_STEPS - 1 - t) : t;
            float l0, h0, l1, h1;
            unpack2(a0, l0, h0);
            unpack2(a1, l1, h1);
            *reinterpret_cast<float2*>(gxbase + ((size_t)b * T_STEPS + n) * 256 + r0) =
                make_float2(l0 + h0, l1 + h1);
        }
    }
}

// ---------------------------------------------------------------------------
// Recurrent: grid 256 = (dir:2) x (bg:128 pairs), block 256, 2 CTAs/SM.
//   Thread: kq = tid>>6 (k-quarter, 16 h-dims), rg = tid&63 -> 4 gate rows,
//   both seqs. 2 __syncthreads per step.
// ---------------------------------------------------------------------------
__global__ void __launch_bounds__(256, 2)
recur_kernel(const float* __restrict__ W_hh_f,
             const float* __restrict__ W_hh_b) {
    const int dir = blockIdx.x >> 7;
    const int bg  = blockIdx.x & 127;
    const int tid = threadIdx.x;
    const int kq  = tid >> 6;          // k-quarter: h dims [16kq, 16kq+16)
    const int rg  = tid & 63;
    const int r0  = 4 * rg;            // 4 consecutive gate rows

    __shared__ __align__(16) float hbuf[2][HID];     // h_t per seq
    __shared__ __align__(16) float gps[2][4][256];   // partials [seq][kq][gate]

    const float* W_hh = dir ? W_hh_b : W_hh_f;

    // weights: 4 rows x 16 dims = 8 packed pairs per row (64 regs total)
    ull wh0[8], wh1[8], wh2[8], wh3[8];
#pragma unroll
    for (int i = 0; i < 8; i++) {
        float2 p0 = *reinterpret_cast<const float2*>(W_hh + (size_t)(r0 + 0) * HID + kq * 16 + 2 * i);
        float2 p1 = *reinterpret_cast<const float2*>(W_hh + (size_t)(r0 + 1) * HID + kq * 16 + 2 * i);
        float2 p2 = *reinterpret_cast<const float2*>(W_hh + (size_t)(r0 + 2) * HID + kq * 16 + 2 * i);
        float2 p3 = *reinterpret_cast<const float2*>(W_hh + (size_t)(r0 + 3) * HID + kq * 16 + 2 * i);
        wh0[i] = pack2(p0.x, p0.y);
        wh1[i] = pack2(p1.x, p1.y);
        wh2[i] = pack2(p2.x, p2.y);
        wh3[i] = pack2(p3.x, p3.y);
    }

    // gx stream (kq==0 threads only): 1 float4 (4 rows) per seq per step
    const float* gxb = dir ? g_gx1 : g_gx0;
    const float* gq0 = gxb + ((size_t)(bg * 2 + 0) * T_STEPS) * 256 + r0;
    const float* gq1 = gxb + ((size_t)(bg * 2 + 1) * T_STEPS) * 256 + r0;

    float4 g0 = make_float4(0.f, 0.f, 0.f, 0.f);
    float4 g1 = make_float4(0.f, 0.f, 0.f, 0.f);
    if (kq == 0) {
        g0 = *reinterpret_cast<const float4*>(gq0);   // gx(0)
        g1 = *reinterpret_cast<const float4*>(gq1);
        gq0 += 256;                                   // -> gx(1)
        gq1 += 256;
    }

    const int s_ep = tid >> 6;   // epilogue mapping (tid<128 -> s_ep in {0,1})
    const int j_ep = tid & 63;
    float cst = 0.0f;
    if (tid < 128) hbuf[s_ep][j_ep] = 0.0f;
    __syncthreads();

    for (int t = 0; t < T_STEPS; t++) {
        // ---- phase A: gate h-partials (4 rows x k-quarter x 2 seqs) ----
        ull a00, a01, a02, a03, a10, a11, a12, a13;
        if (kq == 0) {
            a00 = pack2(g0.x, 0.f); a01 = pack2(g0.y, 0.f);
            a02 = pack2(g0.z, 0.f); a03 = pack2(g0.w, 0.f);
            a10 = pack2(g1.x, 0.f); a11 = pack2(g1.y, 0.f);
            a12 = pack2(g1.z, 0.f); a13 = pack2(g1.w, 0.f);
            if (t + 1 < T_STEPS) {                    // prefetch gx(t+1)
                g0 = *reinterpret_cast<const float4*>(gq0);
                g1 = *reinterpret_cast<const float4*>(gq1);
                gq0 += 256;
                gq1 += 256;
            }
        } else {
            a00 = a01 = a02 = a03 = 0ull;
            a10 = a11 = a12 = a13 = 0ull;
        }
        {
            const float* hb0 = &hbuf[0][kq * 16];
            const float* hb1 = &hbuf[1][kq * 16];
#pragma unroll
            for (int c = 0; c < 4; c++) {
                const ulonglong2 v0 = *reinterpret_cast<const ulonglong2*>(hb0 + 4 * c);
                const ulonglong2 v1 = *reinterpret_cast<const ulonglong2*>(hb1 + 4 * c);
                ffma2(a00, wh0[2 * c], v0.x); ffma2(a00, wh0[2 * c + 1], v0.y);
                ffma2(a01, wh1[2 * c], v0.x); ffma2(a01, wh1[2 * c + 1], v0.y);
                ffma2(a02, wh2[2 * c], v0.x); ffma2(a02, wh2[2 * c + 1], v0.y);
                ffma2(a03, wh3[2 * c], v0.x); ffma2(a03, wh3[2 * c + 1], v0.y);
                ffma2(a10, wh0[2 * c], v1.x); ffma2(a10, wh0[2 * c + 1], v1.y);
                ffma2(a11, wh1[2 * c], v1.x); ffma2(a11, wh1[2 * c + 1], v1.y);
                ffma2(a12, wh2[2 * c], v1.x); ffma2(a12, wh2[2 * c + 1], v1.y);
                ffma2(a13, wh3[2 * c], v1.x); ffma2(a13, wh3[2 * c + 1], v1.y);
            }
            float l0, h0, l1, h1, l2, h2, l3, h3;
            unpack2(a00, l0, h0); unpack2(a01, l1, h1);
            unpack2(a02, l2, h2); unpack2(a03, l3, h3);
            *reinterpret_cast<float4*>(&gps[0][kq][r0]) =
                make_float4(l0 + h0, l1 + h1, l2 + h2, l3 + h3);
            unpack2(a10, l0, h0); unpack2(a11, l1, h1);
            unpack2(a12, l2, h2); unpack2(a13, l3, h3);
            *reinterpret_cast<float4*>(&gps[1][kq][r0]) =
                make_float4(l0 + h0, l1 + h1, l2 + h2, l3 + h3);
        }
        __syncthreads();   // BAR A: gps(t) ready; hbuf reads retired

        // ---- phase B: epilogue (tid<128), 1 cell ----
        if (tid < 128) {
            const float gi = gps[s_ep][0][j_ep]       + gps[s_ep][1][j_ep]
                           + gps[s_ep][2][j_ep]       + gps[s_ep][3][j_ep];
            const float gf = gps[s_ep][0][64 + j_ep]  + gps[s_ep][1][64 + j_ep]
                           + gps[s_ep][2][64 + j_ep]  + gps[s_ep][3][64 + j_ep];
            const float gg = gps[s_ep][0][128 + j_ep] + gps[s_ep][1][128 + j_ep]
                           + gps[s_ep][2][128 + j_ep] + gps[s_ep][3][128 + j_ep];
            const float go = gps[s_ep][0][192 + j_ep] + gps[s_ep][1][192 + j_ep]
                           + gps[s_ep][2][192 + j_ep] + gps[s_ep][3][192 + j_ep];

            const float ig = fast_sigmoid(gi);
            const float fg = fast_sigmoid(gf);
            const float og = fast_sigmoid(go);
            const float gt = fast_tanh(gg);
            cst = fg * cst + ig * gt;
            hbuf[s_ep][j_ep] = og * fast_tanh(cst);
        }
        __syncthreads();   // BAR B: h(t+1) published
    }

    if (tid < 128) g_cfin[dir][bg * 2 + s_ep][j_ep] = cst;
}

// ---------------------------------------------------------------------------
__global__ void final_kernel(const float* __restrict__ W_fin,
                             const float* __restrict__ b_fin,
                             float* __restrict__ out) {
    const int b = threadIdx.x;
    float a0 = b_fin[0], a1 = b_fin[1], a2 = b_fin[2];
#pragma unroll
    for (int j = 0; j < HID; j++) {
        const float cf = g_cfin[0][b][j];
        a0 += W_fin[0 * 128 + j] * cf;
        a1 += W_fin[1 * 128 + j] * cf;
        a2 += W_fin[2 * 128 + j] * cf;
    }
#pragma unroll
    for (int j = 0; j < HID; j++) {
        const float cb = g_cfin[1][b][j];
        a0 += W_fin[0 * 128 + 64 + j] * cb;
        a1 += W_fin[1 * 128 + 64 + j] * cb;
        a2 += W_fin[2 * 128 + 64 + j] * cb;
    }
    out[b * 3 + 0] = a0;
    out[b * 3 + 1] = a1;
    out[b * 3 + 2] = a2;
}

extern "C" void kernel_launch(void* const* d_in, const int* in_sizes, int n_in,
                              void* d_out, int out_size) {
    (void)in_sizes; (void)n_in; (void)out_size;
    const float* c      = (const float*)d_in[0];
    const float* W_enc  = (const float*)d_in[1];
    const float* b_enc  = (const float*)d_in[2];
    const float* W_ih_f = (const float*)d_in[3];
    const float* W_hh_f = (const float*)d_in[4];
    const float* b_f    = (const float*)d_in[5];
    const float* W_ih_b = (const float*)d_in[6];
    const float* W_hh_b = (const float*)d_in[7];
    const float* b_b    = (const float*)d_in[8];
    const float* W_fin  = (const float*)d_in[9];
    const float* b_fin  = (const float*)d_in[10];
    float* out = (float*)d_out;

    prepass_kernel<<<2048, 256>>>(c, W_enc, b_enc, W_ih_f, b_f, W_ih_b, b_b);
    pad_kernel<<<1, 32>>>();
    pad_kernel<<<1, 32>>>();
    recur_kernel<<<256, 256>>>(W_hh_f, W_hh_b);
    final_kernel<<<1, 256>>>(W_fin, b_fin, out);
}